// round 9
// baseline (speedup 1.0000x reference)
#include <cuda_runtime.h>
#include <cuda_bf16.h>
#include <math.h>

// Problem constants
#define BB 2
#define TT 1024
#define DD 768
#define HH 12
#define HD 64
#define LL 8
#define FF 3072
#define VV 1024
#define BT (BB*TT)          // 2048
#define D3 (3*DD)           // 2304

// ---------------------------------------------------------------------------
// Scratch buffers (device globals; no allocation allowed)
// ---------------------------------------------------------------------------
__device__ float g_x  [BT * DD];   // residual stream
__device__ float g_h  [BT * DD];   // LN output / final-LN output
__device__ float g_qkv[BT * D3];   // qkv projection
__device__ float g_y  [BT * DD];   // attention output
__device__ float g_f1 [BT * FF];   // FFN hidden

// ---------------------------------------------------------------------------
// Embedding: x[b,t,:] = tok_emb[ids[b,t],:] + pos_emb[t,:]
// ---------------------------------------------------------------------------
__global__ void embed_kernel(const int* __restrict__ ids,
                             const float* __restrict__ tok,
                             const float* __restrict__ pos,
                             float* __restrict__ x)
{
    int idx = blockIdx.x * blockDim.x + threadIdx.x;   // < BT*DD
    int bt = idx / DD;
    int d  = idx - bt * DD;
    int t  = bt & (TT - 1);
    x[idx] = tok[(size_t)ids[bt] * DD + d] + pos[(size_t)t * DD + d];
}

// ---------------------------------------------------------------------------
// LayerNorm (two-pass, exact): one CTA per row, 256 threads, D=768
// ---------------------------------------------------------------------------
__global__ __launch_bounds__(256) void ln_kernel(const float* __restrict__ x,
                                                 const float* __restrict__ w,
                                                 const float* __restrict__ b,
                                                 float* __restrict__ out)
{
    int row = blockIdx.x;
    int tid = threadIdx.x;
    const float* xr = x + (size_t)row * DD;
    __shared__ float red[256];

    float v0 = xr[tid], v1 = xr[tid + 256], v2 = xr[tid + 512];

    red[tid] = v0 + v1 + v2;
    __syncthreads();
    #pragma unroll
    for (int off = 128; off > 0; off >>= 1) {
        if (tid < off) red[tid] += red[tid + off];
        __syncthreads();
    }
    float mu = red[0] * (1.0f / DD);
    __syncthreads();

    float d0 = v0 - mu, d1 = v1 - mu, d2 = v2 - mu;
    red[tid] = d0 * d0 + d1 * d1 + d2 * d2;
    __syncthreads();
    #pragma unroll
    for (int off = 128; off > 0; off >>= 1) {
        if (tid < off) red[tid] += red[tid + off];
        __syncthreads();
    }
    float rstd = rsqrtf(red[0] * (1.0f / DD) + 1e-5f);

    float* orow = out + (size_t)row * DD;
    orow[tid]       = d0 * rstd * w[tid]       + b[tid];
    orow[tid + 256] = d1 * rstd * w[tid + 256] + b[tid + 256];
    orow[tid + 512] = d2 * rstd * w[tid + 512] + b[tid + 512];
}

// ---------------------------------------------------------------------------
// SGEMM: C[M,N] = A[M,K] @ B  (B either [K,N] or, if TB, [N,K] accessed ^T)
// 128x128 tile, BK=16, 8x8 per thread, 256 threads.
// EPI: 0 = plain store
//      1 = +bias, exact GELU
//      2 = +res (residual add; res may alias C)
//      3 = +bias +res
// ---------------------------------------------------------------------------
#define BM 128
#define BN 128
#define BK 16

template<int EPI, bool TB>
__global__ __launch_bounds__(256) void sgemm(const float* __restrict__ A,
                                             const float* __restrict__ Bm,
                                             const float* __restrict__ bias,
                                             const float* __restrict__ res,
                                             float* __restrict__ C,
                                             int M, int N, int K)
{
    __shared__ float As[BK][BM];
    __shared__ float Bs[BK][BN];

    int tid  = threadIdx.x;
    int brow = blockIdx.y * BM;
    int bcol = blockIdx.x * BN;
    int ty = tid >> 4;   // 0..15
    int tx = tid & 15;   // 0..15

    float acc[8][8];
    #pragma unroll
    for (int i = 0; i < 8; i++)
        #pragma unroll
        for (int j = 0; j < 8; j++) acc[i][j] = 0.0f;

    for (int k0 = 0; k0 < K; k0 += BK) {
        // Load A tile [BM x BK], store transposed As[k][m]
        #pragma unroll
        for (int i = 0; i < 2; i++) {
            int s  = tid + i * 256;        // 0..511
            int r  = s >> 2;               // 0..127
            int c4 = (s & 3) * 4;          // 0,4,8,12
            float4 v = *(const float4*)&A[(size_t)(brow + r) * K + k0 + c4];
            As[c4 + 0][r] = v.x; As[c4 + 1][r] = v.y;
            As[c4 + 2][r] = v.z; As[c4 + 3][r] = v.w;
        }
        // Load B tile
        if (!TB) {
            #pragma unroll
            for (int i = 0; i < 2; i++) {
                int s  = tid + i * 256;
                int r  = s >> 5;            // 0..15
                int c4 = (s & 31) * 4;      // 0..124
                *(float4*)&Bs[r][c4] =
                    *(const float4*)&Bm[(size_t)(k0 + r) * N + bcol + c4];
            }
        } else {
            #pragma unroll
            for (int i = 0; i < 2; i++) {
                int s  = tid + i * 256;
                int r  = s >> 2;            // 0..127  (n index)
                int c4 = (s & 3) * 4;       // k offset
                float4 v = *(const float4*)&Bm[(size_t)(bcol + r) * K + k0 + c4];
                Bs[c4 + 0][r] = v.x; Bs[c4 + 1][r] = v.y;
                Bs[c4 + 2][r] = v.z; Bs[c4 + 3][r] = v.w;
            }
        }
        __syncthreads();

        #pragma unroll
        for (int kk = 0; kk < BK; kk++) {
            float a[8], bv[8];
            #pragma unroll
            for (int i = 0; i < 8; i++) a[i]  = As[kk][ty * 8 + i];
            #pragma unroll
            for (int j = 0; j < 8; j++) bv[j] = Bs[kk][tx * 8 + j];
            #pragma unroll
            for (int i = 0; i < 8; i++)
                #pragma unroll
                for (int j = 0; j < 8; j++)
                    acc[i][j] += a[i] * bv[j];
        }
        __syncthreads();
    }

    // Epilogue
    #pragma unroll
    for (int i = 0; i < 8; i++) {
        int r = brow + ty * 8 + i;
        #pragma unroll
        for (int j = 0; j < 8; j++) {
            int c = bcol + tx * 8 + j;
            float v = acc[i][j];
            if (EPI == 1) {
                v += bias[c];
                v = 0.5f * v * (1.0f + erff(v * 0.70710678118654752f));
            } else if (EPI == 2) {
                v += res[(size_t)r * N + c];
            } else if (EPI == 3) {
                v += bias[c] + res[(size_t)r * N + c];
            }
            C[(size_t)r * N + c] = v;
        }
    }
}

// ---------------------------------------------------------------------------
// Causal attention, fp32 flash-style.
// grid = (T/64, B*H), 256 threads. Each CTA: 64 q-rows for one (b,h).
// Online softmax, 4x4 register tiles on a 16x16 thread grid.
// Dynamic smem: Qs,Ks,Vs,Ps each [64][68] floats = 69632 B total.
// ---------------------------------------------------------------------------
#define APAD 68
#define ATTN_SMEM (4 * 64 * APAD * (int)sizeof(float))

__global__ __launch_bounds__(256) void attn_kernel(const float* __restrict__ qkv,
                                                   float* __restrict__ y)
{
    extern __shared__ float sm[];
    float (*Qs)[APAD] = (float(*)[APAD])(sm);
    float (*Ks)[APAD] = (float(*)[APAD])(sm + 1 * 64 * APAD);  // stored [d][c]
    float (*Vs)[APAD] = (float(*)[APAD])(sm + 2 * 64 * APAD);  // stored [j][d]
    float (*Ps)[APAD] = (float(*)[APAD])(sm + 3 * 64 * APAD);  // stored [r][j]

    int qb = blockIdx.x;             // q tile 0..15
    int bh = blockIdx.y;             // 0..23
    int b  = bh / HH, h = bh % HH;
    int tid = threadIdx.x;
    int ty = tid >> 4, tx = tid & 15;

    const float* base = qkv + (size_t)b * TT * D3 + h * HD;

    // Load Q tile [64 x 64]
    #pragma unroll
    for (int i = 0; i < 4; i++) {
        int s  = tid + i * 256;       // 0..1023
        int r  = s >> 4;              // 0..63
        int c4 = (s & 15) * 4;        // 0..60
        *(float4*)&Qs[r][c4] =
            *(const float4*)&base[(size_t)(qb * 64 + r) * D3 + c4];
    }

    float o[4][4];
    float m_run[4], l_run[4];
    #pragma unroll
    for (int i = 0; i < 4; i++) {
        m_run[i] = -INFINITY; l_run[i] = 0.0f;
        #pragma unroll
        for (int j = 0; j < 4; j++) o[i][j] = 0.0f;
    }
    const float scale = 0.125f;      // 1/sqrt(64)

    for (int kb = 0; kb <= qb; kb++) {
        __syncthreads();   // prior P@V done with Ks/Vs; Qs visible after next sync
        // K tile transposed -> Ks[d][c]; V tile natural -> Vs[j][d]
        #pragma unroll
        for (int i = 0; i < 4; i++) {
            int s  = tid + i * 256;
            int r  = s >> 4;
            int c4 = (s & 15) * 4;
            float4 kv = *(const float4*)&base[DD     + (size_t)(kb * 64 + r) * D3 + c4];
            Ks[c4 + 0][r] = kv.x; Ks[c4 + 1][r] = kv.y;
            Ks[c4 + 2][r] = kv.z; Ks[c4 + 3][r] = kv.w;
            *(float4*)&Vs[r][c4] =
                *(const float4*)&base[2 * DD + (size_t)(kb * 64 + r) * D3 + c4];
        }
        __syncthreads();

        // S = Q @ K^T  (4x4 per thread)
        float s4[4][4];
        #pragma unroll
        for (int i = 0; i < 4; i++)
            #pragma unroll
            for (int j = 0; j < 4; j++) s4[i][j] = 0.0f;
        #pragma unroll
        for (int d = 0; d < 64; d++) {
            float a[4], bv[4];
            #pragma unroll
            for (int i = 0; i < 4; i++) a[i]  = Qs[ty * 4 + i][d];
            #pragma unroll
            for (int j = 0; j < 4; j++) bv[j] = Ks[d][tx * 4 + j];
            #pragma unroll
            for (int i = 0; i < 4; i++)
                #pragma unroll
                for (int j = 0; j < 4; j++)
                    s4[i][j] += a[i] * bv[j];
        }

        bool diag = (kb == qb);
        #pragma unroll
        for (int i = 0; i < 4; i++)
            #pragma unroll
            for (int j = 0; j < 4; j++) {
                float v = s4[i][j] * scale;
                if (diag && (tx * 4 + j) > (ty * 4 + i)) v = -INFINITY;
                s4[i][j] = v;
            }

        // Online softmax update per row (16 tx-threads per 4-row group)
        #pragma unroll
        for (int i = 0; i < 4; i++) {
            float mx = fmaxf(fmaxf(s4[i][0], s4[i][1]), fmaxf(s4[i][2], s4[i][3]));
            #pragma unroll
            for (int off = 8; off >= 1; off >>= 1)
                mx = fmaxf(mx, __shfl_xor_sync(0xffffffffu, mx, off, 16));
            float nm    = fmaxf(m_run[i], mx);
            float alpha = expf(m_run[i] - nm);
            float rs = 0.0f;
            #pragma unroll
            for (int j = 0; j < 4; j++) {
                float p = expf(s4[i][j] - nm);
                s4[i][j] = p;
                rs += p;
            }
            #pragma unroll
            for (int off = 8; off >= 1; off >>= 1)
                rs += __shfl_xor_sync(0xffffffffu, rs, off, 16);
            l_run[i] = l_run[i] * alpha + rs;
            m_run[i] = nm;
            #pragma unroll
            for (int j = 0; j < 4; j++) o[i][j] *= alpha;
        }

        // Publish P, then O += P @ V
        #pragma unroll
        for (int i = 0; i < 4; i++)
            *(float4*)&Ps[ty * 4 + i][tx * 4] =
                make_float4(s4[i][0], s4[i][1], s4[i][2], s4[i][3]);
        __syncthreads();

        #pragma unroll
        for (int jj = 0; jj < 64; jj++) {
            float pv[4], vv[4];
            #pragma unroll
            for (int i = 0; i < 4; i++) pv[i] = Ps[ty * 4 + i][jj];
            #pragma unroll
            for (int j = 0; j < 4; j++) vv[j] = Vs[jj][tx * 4 + j];
            #pragma unroll
            for (int i = 0; i < 4; i++)
                #pragma unroll
                for (int j = 0; j < 4; j++)
                    o[i][j] += pv[i] * vv[j];
        }
    }

    // Normalize and store: y[b, t, h*64 + d]
    float* ybase = y + (size_t)b * TT * DD + h * HD;
    #pragma unroll
    for (int i = 0; i < 4; i++) {
        float inv = 1.0f / l_run[i];
        int r = qb * 64 + ty * 4 + i;
        #pragma unroll
        for (int j = 0; j < 4; j++)
            ybase[(size_t)r * DD + tx * 4 + j] = o[i][j] * inv;
    }
}

// ---------------------------------------------------------------------------
// Host orchestration
// ---------------------------------------------------------------------------
extern "C" void kernel_launch(void* const* d_in, const int* in_sizes, int n_in,
                              void* d_out, int out_size)
{
    (void)in_sizes; (void)n_in; (void)out_size;

    const int*   ids  = (const int*)  d_in[0];
    const float* tok  = (const float*)d_in[1];
    const float* pos  = (const float*)d_in[2];
    const float* ln1w = (const float*)d_in[3];
    const float* ln1b = (const float*)d_in[4];
    const float* qkvw = (const float*)d_in[5];
    const float* outw = (const float*)d_in[6];
    const float* ln2w = (const float*)d_in[7];
    const float* ln2b = (const float*)d_in[8];
    const float* w1   = (const float*)d_in[9];
    const float* b1   = (const float*)d_in[10];
    const float* w2   = (const float*)d_in[11];
    const float* b2   = (const float*)d_in[12];
    const float* lnfw = (const float*)d_in[13];
    const float* lnfb = (const float*)d_in[14];
    float* out = (float*)d_out;

    float *x, *h, *qkv, *y, *f1;
    cudaGetSymbolAddress((void**)&x,   g_x);
    cudaGetSymbolAddress((void**)&h,   g_h);
    cudaGetSymbolAddress((void**)&qkv, g_qkv);
    cudaGetSymbolAddress((void**)&y,   g_y);
    cudaGetSymbolAddress((void**)&f1,  g_f1);

    cudaFuncSetAttribute(attn_kernel,
                         cudaFuncAttributeMaxDynamicSharedMemorySize, ATTN_SMEM);

    // Embedding
    embed_kernel<<<(BT * DD) / 256, 256>>>(ids, tok, pos, x);

    for (int l = 0; l < LL; l++) {
        // LN1
        ln_kernel<<<BT, 256>>>(x, ln1w + l * DD, ln1b + l * DD, h);
        // QKV projection: [2048,768] @ [768,2304]
        sgemm<0, false><<<dim3(D3 / BN, BT / BM), 256>>>(
            h, qkvw + (size_t)l * DD * D3, nullptr, nullptr, qkv, BT, D3, DD);
        // Attention
        attn_kernel<<<dim3(TT / 64, BB * HH), 256, ATTN_SMEM>>>(qkv, y);
        // Out projection + residual (in-place on x)
        sgemm<2, false><<<dim3(DD / BN, BT / BM), 256>>>(
            y, outw + (size_t)l * DD * DD, nullptr, x, x, BT, DD, DD);
        // LN2
        ln_kernel<<<BT, 256>>>(x, ln2w + l * DD, ln2b + l * DD, h);
        // FFN1 + bias + exact GELU
        sgemm<1, false><<<dim3(FF / BN, BT / BM), 256>>>(
            h, w1 + (size_t)l * DD * FF, b1 + (size_t)l * FF, nullptr, f1, BT, FF, DD);
        // FFN2 + bias + residual (in-place on x)
        sgemm<3, false><<<dim3(DD / BN, BT / BM), 256>>>(
            f1, w2 + (size_t)l * FF * DD, b2 + (size_t)l * DD, x, x, BT, DD, FF);
    }

    // Final LN
    ln_kernel<<<BT, 256>>>(x, lnfw, lnfb, h);
    // Tied LM head: [2048,768] @ tok_emb[1024,768]^T
    sgemm<0, true><<<dim3(VV / BN, BT / BM), 256>>>(
        h, tok, nullptr, nullptr, out, BT, VV, DD);
}